// round 7
// baseline (speedup 1.0000x reference)
#include <cuda_runtime.h>
#include <math.h>

typedef unsigned long long ull;

// ---------------- f32x2 packed helpers (Blackwell) ----------------
__device__ __forceinline__ ull pk2(float lo, float hi) {
    ull r; asm("mov.b64 %0, {%1,%2};" : "=l"(r) : "f"(lo), "f"(hi)); return r;
}
__device__ __forceinline__ float2 upk2(ull v) {
    float2 r; asm("mov.b64 {%0,%1}, %2;" : "=f"(r.x), "=f"(r.y) : "l"(v)); return r;
}
__device__ __forceinline__ ull ffma2(ull a, ull b, ull c) {
    ull d; asm("fma.rn.f32x2 %0, %1, %2, %3;" : "=l"(d) : "l"(a), "l"(b), "l"(c)); return d;
}

// ---------------- device scratch ----------------
__device__ float2 g_feat2[32 * 128 * 128];    // enc output, [pair][y][x]
__device__ ull    g_SF[16 * 32 * 16384];      // (I + B_ph A_ph) @ feat, [ph][cpair][pos]
__device__ float2 g_out2[32 * 512 * 512];     // pre-tail features, [pair][y][x]
__device__ float4 g_pred4[512 * 512];         // tail output, [y][x] -> (r,g,b,_)
__device__ float  g_off[16 * 2];              // per-phase offsets (ch0=x, ch1=y)
__device__ float  g_A[16 * 8 * 64];           // per-phase compress  [ph][k][c]
__device__ float  g_B[16 * 64 * 8];           // per-phase expand    [ph][c][k]

// ---------------- K1: enc conv3x3, pad=1, 3->64 ch ----------------
__global__ void __launch_bounds__(256) enc_kernel(const float* __restrict__ inp,
                                                  const float* __restrict__ w,
                                                  const float* __restrict__ b) {
    __shared__ float sw[54];
    __shared__ float sb[2];
    int idx = blockIdx.x * 256 + threadIdx.x;       // pair*16384 + y*128 + x
    int pair = idx >> 14;                            // constant per block
    if (threadIdx.x < 54) sw[threadIdx.x] = w[pair * 54 + threadIdx.x];
    if (threadIdx.x < 2)  sb[threadIdx.x] = b[pair * 2 + threadIdx.x];
    __syncthreads();
    int rem = idx & 16383;
    int y = rem >> 7;
    int x = rem & 127;
    float a0 = sb[0], a1 = sb[1];
#pragma unroll
    for (int ci = 0; ci < 3; ci++) {
        const float* ip = inp + ci * 16384;
        const float* w0 = sw + ci * 9;
        const float* w1 = sw + 27 + ci * 9;
#pragma unroll
        for (int ky = 0; ky < 3; ky++) {
            int yy = y + ky - 1;
            if (yy < 0 || yy > 127) continue;
#pragma unroll
            for (int kx = 0; kx < 3; kx++) {
                int xx = x + kx - 1;
                if (xx < 0 || xx > 127) continue;
                float v = __ldg(ip + yy * 128 + xx);
                a0 += v * w0[ky * 3 + kx];
                a1 += v * w1[ky * 3 + kx];
            }
        }
    }
    g_feat2[idx] = make_float2(a0, a1);
}

// ---------------- K2: per-phase MLP -> off, A, B ----------------
__global__ void phase_kernel(const float* __restrict__ w1, const float* __restrict__ b1,
                             const float* __restrict__ w2, const float* __restrict__ b2,
                             const float* __restrict__ rw, const float* __restrict__ rb,
                             const float* __restrict__ ow, const float* __restrict__ ob,
                             const float* __restrict__ wc, const float* __restrict__ we) {
    __shared__ float s1[64], s2[64], sr[4];
    int c = threadIdx.x;
    int ph = blockIdx.x;                 // ph = (y%4)*4 + (x%4)
    float chv = ((ph >> 2) + 0.5f) * 0.25f - 0.5f;
    float cwv = ((ph & 3)  + 0.5f) * 0.25f - 0.5f;
    float e1 = b1[c] + w1[c * 4 + 0] * 0.25f + w1[c * 4 + 1] * 0.25f
                     + w1[c * 4 + 2] * chv   + w1[c * 4 + 3] * cwv;
    s1[c] = fmaxf(e1, 0.f);
    __syncthreads();
    float e2 = b2[c];
    for (int d = 0; d < 64; d++) e2 += w2[c * 64 + d] * s1[d];
    s2[c] = fmaxf(e2, 0.f);
    __syncthreads();
    if (c < 4) {
        float z = rb[c];
        for (int d = 0; d < 64; d++) z += rw[c * 64 + d] * s2[d];
        sr[c] = 1.f / (1.f + expf(-z));
    } else if (c < 6) {
        int o = c - 4;
        float z = ob[o];
        for (int d = 0; d < 64; d++) z += ow[o * 64 + d] * s2[d];
        g_off[ph * 2 + o] = z;
    }
    __syncthreads();
    float r0 = sr[0], r1 = sr[1], r2 = sr[2], r3 = sr[3];
    for (int t = c; t < 512; t += 64) {
        g_A[ph * 512 + t] = r0 * wc[t] + r1 * wc[512 + t] + r2 * wc[1024 + t] + r3 * wc[1536 + t];
        g_B[ph * 512 + t] = r0 * we[t] + r1 * we[512 + t] + r2 * we[1024 + t] + r3 * we[1536 + t];
    }
}

// ---------------- K2b: SF[ph][cp][pos] = feat + B_ph (A_ph feat) ----------------
__global__ void __launch_bounds__(256) sf_kernel() {
    __shared__ ull sA2[8][32];   // [k][cpair]  pk2(A[k][2i], A[k][2i+1])
    __shared__ ull sB2[32][8];   // [cpair][k]  pk2(B[2i][k], B[2i+1][k])
    int tid = threadIdx.x;
    int ph = blockIdx.x >> 6;                // 16 phases x 64 chunks
    int chunk = blockIdx.x & 63;
    sA2[tid >> 5][tid & 31] = ((const ull*)g_A)[ph * 256 + tid];
    {
        int i = tid >> 3, k = tid & 7;
        sB2[i][k] = pk2(g_B[ph * 512 + 16 * i + k],
                        g_B[ph * 512 + 16 * i + 8 + k]);
    }
    __syncthreads();
    int pos = chunk * 256 + tid;

    // pass 1: m_k = sum_c A[k][c] feat[c]
    ull acc[8];
#pragma unroll
    for (int k = 0; k < 8; k++) acc[k] = 0ULL;
#pragma unroll
    for (int i = 0; i < 32; i++) {
        ull f = __ldg((const ull*)g_feat2 + (i << 14) + pos);
#pragma unroll
        for (int k = 0; k < 8; k++) acc[k] = ffma2(sA2[k][i], f, acc[k]);
    }
    ull mk[8];
#pragma unroll
    for (int k = 0; k < 8; k++) {
        float2 a = upk2(acc[k]);
        float m = a.x + a.y;
        mk[k] = pk2(m, m);
    }

    // pass 2: SF = feat + B m  (feat re-load hits L1)
    ull* dst = g_SF + ph * 32 * 16384 + pos;
#pragma unroll
    for (int i = 0; i < 32; i++) {
        ull t = __ldg((const ull*)g_feat2 + (i << 14) + pos);
#pragma unroll
        for (int k = 0; k < 8; k++) t = ffma2(sB2[i][k], mk[k], t);
        dst[i * 16384] = t;
    }
}

// ---------------- bilinear coordinate pack ----------------
struct Bil {
    ull w00, w01, w10, w11;
    int o00, o01, o10, o11;
};
__device__ __forceinline__ Bil make_bil(int x, int y, float offx, float offy) {
    Bil r;
    const float C2 = 2.0f / 127.0f;
    float gx = ((x + 0.5f) * 0.25f - 0.5f) * C2 - 1.0f + offx * C2;
    float gy = ((y + 0.5f) * 0.25f - 0.5f) * C2 - 1.0f + offy * C2;
    float px = (gx + 1.0f) * 63.5f;
    float py = (gy + 1.0f) * 63.5f;
    float fx = floorf(px), fy = floorf(py);
    float wx1 = px - fx, wx0 = 1.f - wx1;
    float wy1 = py - fy, wy0 = 1.f - wy1;
    int ix0 = (int)fx, iy0 = (int)fy, ix1 = ix0 + 1, iy1 = iy0 + 1;
    float mx0 = (ix0 >= 0 && ix0 < 128) ? 1.f : 0.f;
    float mx1 = (ix1 >= 0 && ix1 < 128) ? 1.f : 0.f;
    float my0 = (iy0 >= 0 && iy0 < 128) ? 1.f : 0.f;
    float my1 = (iy1 >= 0 && iy1 < 128) ? 1.f : 0.f;
    int cx0 = min(127, max(0, ix0)), cx1 = min(127, max(0, ix1));
    int cy0 = min(127, max(0, iy0)), cy1 = min(127, max(0, iy1));
    float f00 = wy0 * wx0 * my0 * mx0, f01 = wy0 * wx1 * my0 * mx1;
    float f10 = wy1 * wx0 * my1 * mx0, f11 = wy1 * wx1 * my1 * mx1;
    r.w00 = pk2(f00, f00); r.w01 = pk2(f01, f01);
    r.w10 = pk2(f10, f10); r.w11 = pk2(f11, f11);
    r.o00 = cy0 * 128 + cx0; r.o01 = cy0 * 128 + cx1;
    r.o10 = cy1 * 128 + cx0; r.o11 = cy1 * 128 + cx1;
    return r;
}
__device__ __forceinline__ ull bil4(const ull* __restrict__ P, const Bil& b) {
    ull t0 = ffma2(b.w00, __ldg(P + b.o00), 0ULL);
    ull t1 = ffma2(b.w01, __ldg(P + b.o01), 0ULL);
    t0 = ffma2(b.w10, __ldg(P + b.o10), t0);
    t1 = ffma2(b.w11, __ldg(P + b.o11), t1);
    float2 a = upk2(t0), c = upk2(t1);
    return pk2(a.x + c.x, a.y + c.y);
}

// ---------------- K3: out2 = bilinear(SF), 2 px/thread, cpair-split ----------------
__global__ void __launch_bounds__(256) main_kernel() {
    __shared__ float sOff[8];
    int tid = threadIdx.x;
    int y = blockIdx.x & 511;
    int half = blockIdx.x >> 9;              // 0 or 1: cpairs 0-15 / 16-31
    int j = y & 3;
    if (tid < 8) sOff[tid] = g_off[j * 8 + tid];
    __syncthreads();

    int xA = tid;            // pixel A
    int xB = tid + 256;      // pixel B (same phase)
    int pi = tid & 3;
    int ph = j * 4 + pi;
    float offx = sOff[pi * 2 + 0];
    float offy = sOff[pi * 2 + 1];
    Bil bA = make_bil(xA, y, offx, offy);
    Bil bB = make_bil(xB, y, offx, offy);

    const ull* S = g_SF + (ph * 32 + half * 16) * 16384;
    int baseA = y * 512 + xA;
    int baseB = y * 512 + xB;
    ull* O = (ull*)g_out2 + (half << 22);    // half*16*262144
#pragma unroll
    for (int i = 0; i < 16; i++) {
        const ull* P = S + i * 16384;
        ull tA = bil4(P, bA);
        ull tB = bil4(P, bB);
        O[(i << 18) + baseA] = tA;
        O[(i << 18) + baseB] = tB;
    }
}

// ---------------- K4: tail conv3x3, 64->3 ch, 4-row streaming ----------------
__global__ void __launch_bounds__(128) tail_kernel(const float* __restrict__ tw,
                                                   const float* __restrict__ tb) {
    __shared__ __align__(16) ull sw2[3][32][9];     // packed (c0,c1) weights
    int tid = threadIdx.x;
    for (int i = tid; i < 864; i += 128) {
        int o = i / 288, rem = i % 288, p = rem / 9, t = rem % 9;
        sw2[o][p][t] = pk2(tw[o * 576 + (2 * p) * 9 + t],
                           tw[o * 576 + (2 * p + 1) * 9 + t]);
    }
    __syncthreads();

    int x = blockIdx.x * 128 + tid;
    int y0 = blockIdx.y * 4;
    bool xm = x > 0, xp = x < 511;
    ull acc[4][3];
#pragma unroll
    for (int oy = 0; oy < 4; oy++)
#pragma unroll
        for (int o = 0; o < 3; o++) acc[oy][o] = 0ULL;

    for (int pair = 0; pair < 32; pair++) {
        const ull* P = (const ull*)g_out2 + (pair << 18);
#pragma unroll
        for (int r = 0; r < 6; r++) {
            int yy = y0 - 1 + r;
            bool vy = (yy >= 0) && (yy < 512);
            int row = yy * 512 + x;
            ull v0 = (vy && xm) ? __ldg(P + row - 1) : 0ULL;
            ull v1 = vy ? __ldg(P + row) : 0ULL;
            ull v2 = (vy && xp) ? __ldg(P + row + 1) : 0ULL;
#pragma unroll
            for (int oy = 0; oy < 4; oy++) {
                int ky = r - oy;
                if (ky < 0 || ky > 2) continue;
#pragma unroll
                for (int o = 0; o < 3; o++) {
                    ull a = acc[oy][o];
                    a = ffma2(sw2[o][pair][ky * 3 + 0], v0, a);
                    a = ffma2(sw2[o][pair][ky * 3 + 1], v1, a);
                    a = ffma2(sw2[o][pair][ky * 3 + 2], v2, a);
                    acc[oy][o] = a;
                }
            }
        }
    }
#pragma unroll
    for (int oy = 0; oy < 4; oy++) {
        int row = (y0 + oy) * 512 + x;
        float2 a0 = upk2(acc[oy][0]);
        float2 a1 = upk2(acc[oy][1]);
        float2 a2 = upk2(acc[oy][2]);
        g_pred4[row] = make_float4(__ldg(tb + 0) + a0.x + a0.y,
                                   __ldg(tb + 1) + a1.x + a1.y,
                                   __ldg(tb + 2) + a2.x + a2.y, 0.f);
    }
}

// ---------------- K5: query gather ----------------
__global__ void gather_kernel(const float* __restrict__ coord,
                              const float* __restrict__ cell,
                              float* __restrict__ out) {
    int q = blockIdx.x * 256 + threadIdx.x;
    float2 cd = __ldg((const float2*)coord + q);
    float2 cl = __ldg((const float2*)cell + q);
    const float LO = -0.999999f, HI = 0.999999f;
    float gyq = fminf(fmaxf(cd.x - cl.x * 0.5f + 1e-6f, LO), HI);
    float gxq = fminf(fmaxf(cd.y - cl.y * 0.5f + 1e-6f, LO), HI);
    int xi = (int)rintf((gxq + 1.0f) * 0.5f * 511.0f);
    int yi = (int)rintf((gyq + 1.0f) * 0.5f * 511.0f);
    xi = min(511, max(0, xi));
    yi = min(511, max(0, yi));
    float4 v = __ldg(&g_pred4[(yi << 9) + xi]);
    out[q * 3 + 0] = v.x;
    out[q * 3 + 1] = v.y;
    out[q * 3 + 2] = v.z;
}

// ---------------- launch ----------------
extern "C" void kernel_launch(void* const* d_in, const int* in_sizes, int n_in,
                              void* d_out, int out_size) {
    const float* inp   = (const float*)d_in[0];
    const float* coord = (const float*)d_in[1];
    const float* cell  = (const float*)d_in[2];
    const float* enc_w = (const float*)d_in[3];
    const float* enc_b = (const float*)d_in[4];
    const float* w1    = (const float*)d_in[5];
    const float* b1    = (const float*)d_in[6];
    const float* w2    = (const float*)d_in[7];
    const float* b2    = (const float*)d_in[8];
    const float* rw    = (const float*)d_in[9];
    const float* rb    = (const float*)d_in[10];
    const float* ow    = (const float*)d_in[11];
    const float* ob    = (const float*)d_in[12];
    const float* tw    = (const float*)d_in[13];
    const float* tb    = (const float*)d_in[14];
    const float* wc    = (const float*)d_in[15];
    const float* we    = (const float*)d_in[16];
    float* out = (float*)d_out;

    enc_kernel<<<2048, 256>>>(inp, enc_w, enc_b);
    phase_kernel<<<16, 64>>>(w1, b1, w2, b2, rw, rb, ow, ob, wc, we);
    sf_kernel<<<1024, 256>>>();
    main_kernel<<<1024, 256>>>();
    tail_kernel<<<dim3(4, 128), 128>>>(tw, tb);
    gather_kernel<<<1024, 256>>>(coord, cell, out);
}

// round 8
// speedup vs baseline: 1.1756x; 1.1756x over previous
#include <cuda_runtime.h>
#include <math.h>

typedef unsigned long long ull;

// ---------------- f32x2 packed helpers (Blackwell) ----------------
__device__ __forceinline__ ull pk2(float lo, float hi) {
    ull r; asm("mov.b64 %0, {%1,%2};" : "=l"(r) : "f"(lo), "f"(hi)); return r;
}
__device__ __forceinline__ float2 upk2(ull v) {
    float2 r; asm("mov.b64 {%0,%1}, %2;" : "=f"(r.x), "=f"(r.y) : "l"(v)); return r;
}
__device__ __forceinline__ ull ffma2(ull a, ull b, ull c) {
    ull d; asm("fma.rn.f32x2 %0, %1, %2, %3;" : "=l"(d) : "l"(a), "l"(b), "l"(c)); return d;
}
__device__ __forceinline__ ull swap2(ull v) {
    float2 a = upk2(v); return pk2(a.y, a.x);
}

// ---------------- device scratch ----------------
__device__ float2 g_feat2[32 * 128 * 128];    // enc output, [pair][y][x]
__device__ float2 g_out2[32 * 512 * 512];     // pre-tail features, [pair][y][x]
__device__ float4 g_pred4[512 * 512];         // tail output, [y][x] -> (r,g,b,_)
__device__ float  g_off[16 * 2];              // per-phase offsets (ch0=x, ch1=y)
__device__ float  g_A[16 * 8 * 64];           // per-phase compress  [ph][k][c]
__device__ float  g_B[16 * 64 * 8];           // per-phase expand    [ph][c][k]
__device__ ull    g_AF2[16 * 4 * 16384];      // A_ph @ feat, [ph][kpair][pos]
__device__ ull    g_mid[512 * 512 * 4];       // per-pixel mid, 4 packed k-pairs

// ---------------- K1: enc conv3x3, pad=1, 3->64 ch ----------------
__global__ void __launch_bounds__(256) enc_kernel(const float* __restrict__ inp,
                                                  const float* __restrict__ w,
                                                  const float* __restrict__ b) {
    __shared__ float sw[54];
    __shared__ float sb[2];
    int idx = blockIdx.x * 256 + threadIdx.x;       // pair*16384 + y*128 + x
    int pair = idx >> 14;                            // constant per block
    if (threadIdx.x < 54) sw[threadIdx.x] = w[pair * 54 + threadIdx.x];
    if (threadIdx.x < 2)  sb[threadIdx.x] = b[pair * 2 + threadIdx.x];
    __syncthreads();
    int rem = idx & 16383;
    int y = rem >> 7;
    int x = rem & 127;
    float a0 = sb[0], a1 = sb[1];
#pragma unroll
    for (int ci = 0; ci < 3; ci++) {
        const float* ip = inp + ci * 16384;
        const float* w0 = sw + ci * 9;
        const float* w1 = sw + 27 + ci * 9;
#pragma unroll
        for (int ky = 0; ky < 3; ky++) {
            int yy = y + ky - 1;
            if (yy < 0 || yy > 127) continue;
#pragma unroll
            for (int kx = 0; kx < 3; kx++) {
                int xx = x + kx - 1;
                if (xx < 0 || xx > 127) continue;
                float v = __ldg(ip + yy * 128 + xx);
                a0 += v * w0[ky * 3 + kx];
                a1 += v * w1[ky * 3 + kx];
            }
        }
    }
    g_feat2[idx] = make_float2(a0, a1);
}

// ---------------- K2: per-phase MLP -> off, A, B ----------------
__global__ void phase_kernel(const float* __restrict__ w1, const float* __restrict__ b1,
                             const float* __restrict__ w2, const float* __restrict__ b2,
                             const float* __restrict__ rw, const float* __restrict__ rb,
                             const float* __restrict__ ow, const float* __restrict__ ob,
                             const float* __restrict__ wc, const float* __restrict__ we) {
    __shared__ float s1[64], s2[64], sr[4];
    int c = threadIdx.x;
    int ph = blockIdx.x;                 // ph = (y%4)*4 + (x%4)
    float chv = ((ph >> 2) + 0.5f) * 0.25f - 0.5f;
    float cwv = ((ph & 3)  + 0.5f) * 0.25f - 0.5f;
    float e1 = b1[c] + w1[c * 4 + 0] * 0.25f + w1[c * 4 + 1] * 0.25f
                     + w1[c * 4 + 2] * chv   + w1[c * 4 + 3] * cwv;
    s1[c] = fmaxf(e1, 0.f);
    __syncthreads();
    float e2 = b2[c];
    for (int d = 0; d < 64; d++) e2 += w2[c * 64 + d] * s1[d];
    s2[c] = fmaxf(e2, 0.f);
    __syncthreads();
    if (c < 4) {
        float z = rb[c];
        for (int d = 0; d < 64; d++) z += rw[c * 64 + d] * s2[d];
        sr[c] = 1.f / (1.f + expf(-z));
    } else if (c < 6) {
        int o = c - 4;
        float z = ob[o];
        for (int d = 0; d < 64; d++) z += ow[o * 64 + d] * s2[d];
        g_off[ph * 2 + o] = z;
    }
    __syncthreads();
    float r0 = sr[0], r1 = sr[1], r2 = sr[2], r3 = sr[3];
    for (int t = c; t < 512; t += 64) {
        g_A[ph * 512 + t] = r0 * wc[t] + r1 * wc[512 + t] + r2 * wc[1024 + t] + r3 * wc[1536 + t];
        g_B[ph * 512 + t] = r0 * we[t] + r1 * we[512 + t] + r2 * we[1024 + t] + r3 * we[1536 + t];
    }
}

// ---------------- K2b: AF[ph][kpair][pos] = packed A_ph @ feat ----------------
__global__ void __launch_bounds__(256) af_kernel() {
    __shared__ ull sA2[256];                 // [k][cpair] for this phase
    int tid = threadIdx.x;
    int ph = blockIdx.x >> 6;                // 16 phases x 64 chunks
    int chunk = blockIdx.x & 63;
    sA2[tid] = ((const ull*)g_A)[ph * 256 + tid];
    __syncthreads();
    int pos = chunk * 256 + tid;

    ull f2[32];
#pragma unroll
    for (int i = 0; i < 32; i++)
        f2[i] = __ldg((const ull*)g_feat2 + (i << 14) + pos);

    float m[8];
#pragma unroll
    for (int k = 0; k < 8; k++) {
        ull acc = 0ULL;
#pragma unroll
        for (int i = 0; i < 32; i++) acc = ffma2(sA2[k * 32 + i], f2[i], acc);
        float2 a = upk2(acc);
        m[k] = a.x + a.y;
    }
#pragma unroll
    for (int kp = 0; kp < 4; kp++)
        g_AF2[(ph * 4 + kp) * 16384 + pos] = pk2(m[2 * kp], m[2 * kp + 1]);
}

// ---------------- bilinear coordinate pack ----------------
struct Bil {
    ull w00, w01, w10, w11;
    int o00, o01, o10, o11;
};
__device__ __forceinline__ Bil make_bil(int x, int y, float offx, float offy) {
    Bil r;
    const float C2 = 2.0f / 127.0f;
    float gx = ((x + 0.5f) * 0.25f - 0.5f) * C2 - 1.0f + offx * C2;
    float gy = ((y + 0.5f) * 0.25f - 0.5f) * C2 - 1.0f + offy * C2;
    float px = (gx + 1.0f) * 63.5f;
    float py = (gy + 1.0f) * 63.5f;
    float fx = floorf(px), fy = floorf(py);
    float wx1 = px - fx, wx0 = 1.f - wx1;
    float wy1 = py - fy, wy0 = 1.f - wy1;
    int ix0 = (int)fx, iy0 = (int)fy, ix1 = ix0 + 1, iy1 = iy0 + 1;
    float mx0 = (ix0 >= 0 && ix0 < 128) ? 1.f : 0.f;
    float mx1 = (ix1 >= 0 && ix1 < 128) ? 1.f : 0.f;
    float my0 = (iy0 >= 0 && iy0 < 128) ? 1.f : 0.f;
    float my1 = (iy1 >= 0 && iy1 < 128) ? 1.f : 0.f;
    int cx0 = min(127, max(0, ix0)), cx1 = min(127, max(0, ix1));
    int cy0 = min(127, max(0, iy0)), cy1 = min(127, max(0, iy1));
    float f00 = wy0 * wx0 * my0 * mx0, f01 = wy0 * wx1 * my0 * mx1;
    float f10 = wy1 * wx0 * my1 * mx0, f11 = wy1 * wx1 * my1 * mx1;
    r.w00 = pk2(f00, f00); r.w01 = pk2(f01, f01);
    r.w10 = pk2(f10, f10); r.w11 = pk2(f11, f11);
    r.o00 = cy0 * 128 + cx0; r.o01 = cy0 * 128 + cx1;
    r.o10 = cy1 * 128 + cx0; r.o11 = cy1 * 128 + cx1;
    return r;
}
__device__ __forceinline__ ull bil4(const ull* __restrict__ P, const Bil& b) {
    ull t0 = ffma2(b.w00, __ldg(P + b.o00), 0ULL);
    ull t1 = ffma2(b.w01, __ldg(P + b.o01), 0ULL);
    t0 = ffma2(b.w10, __ldg(P + b.o10), t0);
    t1 = ffma2(b.w11, __ldg(P + b.o11), t1);
    float2 a = upk2(t0), c = upk2(t1);
    return pk2(a.x + c.x, a.y + c.y);
}

// ---------------- K2c: per-pixel mid via AF bilinear ----------------
__global__ void __launch_bounds__(256) mid_kernel() {
    __shared__ float sOff[8];
    int tid = threadIdx.x;
    int y = blockIdx.x;
    int j = y & 3;
    if (tid < 8) sOff[tid] = g_off[j * 8 + tid];
    __syncthreads();
    int pi = tid & 3;
    int ph = j * 4 + pi;
    float offx = sOff[pi * 2 + 0];
    float offy = sOff[pi * 2 + 1];
    Bil bA = make_bil(tid, y, offx, offy);
    Bil bB = make_bil(tid + 256, y, offx, offy);
    const ull* AFp = g_AF2 + ph * 4 * 16384;
    ull MA[4], MB[4];
#pragma unroll
    for (int kp = 0; kp < 4; kp++) {
        const ull* Q = AFp + kp * 16384;
        MA[kp] = bil4(Q, bA);
        MB[kp] = bil4(Q, bB);
    }
    ull* dA = g_mid + (size_t)(y * 512 + tid) * 4;
    ((ulonglong2*)dA)[0] = make_ulonglong2(MA[0], MA[1]);
    ((ulonglong2*)dA)[1] = make_ulonglong2(MA[2], MA[3]);
    ull* dB = dA + 1024;   // (x+256)*4
    ((ulonglong2*)dB)[0] = make_ulonglong2(MB[0], MB[1]);
    ((ulonglong2*)dB)[1] = make_ulonglong2(MB[2], MB[3]);
}

// ---------------- K3: out2 = bil(feat) + B*mid, row x cpair-group blocks ----------------
__global__ void __launch_bounds__(256) main_kernel() {
    // E/O-packed B for 8 cpairs of this group: [ii][kp][eo][pi]
    __shared__ ull sB2[8][4][2][4];
    __shared__ float sOff[8];
    int tid = threadIdx.x;
    int y = blockIdx.x;
    int g = blockIdx.y;                  // cpair group 0..3
    int j = y & 3;
    {
        int ii = tid >> 5, kp = (tid >> 3) & 3, eo = (tid >> 2) & 1, pi2 = tid & 3;
        int ph2 = j * 4 + pi2;
        int c0 = 2 * (g * 8 + ii), c1 = c0 + 1;
        int a = 2 * kp, b = a + 1;
        const float* Bp = g_B + ph2 * 512;
        ull v = (eo == 0) ? pk2(Bp[c0 * 8 + a], Bp[c1 * 8 + b])
                          : pk2(Bp[c0 * 8 + b], Bp[c1 * 8 + a]);
        sB2[ii][kp][eo][pi2] = v;
    }
    if (tid < 8) sOff[tid] = g_off[j * 8 + tid];
    __syncthreads();

    int pi = tid & 3;
    float offx = sOff[pi * 2 + 0];
    float offy = sOff[pi * 2 + 1];
    Bil bA = make_bil(tid, y, offx, offy);
    Bil bB = make_bil(tid + 256, y, offx, offy);

    int baseA = y * 512 + tid;
    int baseB = baseA + 256;
    // load mid (coalesced LDG.128) and build swapped copies
    ull MA[4], SA[4], MB[4], SB[4];
    {
        const ulonglong2* mA = (const ulonglong2*)(g_mid + (size_t)baseA * 4);
        ulonglong2 a0 = __ldg(mA), a1 = __ldg(mA + 1);
        MA[0] = a0.x; MA[1] = a0.y; MA[2] = a1.x; MA[3] = a1.y;
        const ulonglong2* mB = (const ulonglong2*)(g_mid + (size_t)baseB * 4);
        ulonglong2 b0 = __ldg(mB), b1 = __ldg(mB + 1);
        MB[0] = b0.x; MB[1] = b0.y; MB[2] = b1.x; MB[3] = b1.y;
#pragma unroll
        for (int kp = 0; kp < 4; kp++) { SA[kp] = swap2(MA[kp]); SB[kp] = swap2(MB[kp]); }
    }

#pragma unroll
    for (int ii = 0; ii < 8; ii++) {
        int i = g * 8 + ii;
        const ull* F = (const ull*)g_feat2 + (i << 14);
        ull tA = bil4(F, bA);
        ull tB = bil4(F, bB);
#pragma unroll
        for (int kp = 0; kp < 4; kp++) {
            ull e = sB2[ii][kp][0][pi];
            ull o = sB2[ii][kp][1][pi];
            tA = ffma2(e, MA[kp], tA); tA = ffma2(o, SA[kp], tA);
            tB = ffma2(e, MB[kp], tB); tB = ffma2(o, SB[kp], tB);
        }
        ((ull*)g_out2)[(i << 18) + baseA] = tA;
        ((ull*)g_out2)[(i << 18) + baseB] = tB;
    }
}

// ---------------- K4: tail conv3x3 via smem tiles, 128x8 out per block ----------------
__global__ void __launch_bounds__(256) tail_kernel(const float* __restrict__ tw,
                                                   const float* __restrict__ tb) {
    __shared__ ull swp[32][9][4];        // [cpair][tap][o], o padded to 4
    __shared__ ull tile[10][132];        // halo 130x10, padded stride
    int tid = threadIdx.x;
    for (int t = tid; t < 864; t += 256) {
        int cp = t / 27, rem = t % 27, tap = rem / 3, o = rem % 3;
        swp[cp][tap][o] = pk2(tw[o * 576 + (2 * cp) * 9 + tap],
                              tw[o * 576 + (2 * cp + 1) * 9 + tap]);
    }
    int x0 = blockIdx.x * 128;
    int y0 = blockIdx.y * 8;
    int xl = tid & 127;
    int yq = (tid >> 7) * 4;             // 0 or 4
    ull acc[4][3];
#pragma unroll
    for (int oy = 0; oy < 4; oy++)
#pragma unroll
        for (int o = 0; o < 3; o++) acc[oy][o] = 0ULL;
    __syncthreads();

    for (int cp = 0; cp < 32; cp++) {
        const ull* P = (const ull*)g_out2 + (cp << 18);
        // cooperative halo load: 10 rows x 130 cols
        for (int t = tid; t < 1300; t += 256) {
            int r = t / 130, cc = t % 130;
            int yy = y0 - 1 + r, xx = x0 - 1 + cc;
            ull v = 0ULL;
            if (yy >= 0 && yy < 512 && xx >= 0 && xx < 512)
                v = __ldg(P + yy * 512 + xx);
            tile[r][cc] = v;
        }
        __syncthreads();
        // conv: this thread's 4 output rows yq..yq+3 at column xl
        ull v[6][3];
#pragma unroll
        for (int r2 = 0; r2 < 6; r2++)
#pragma unroll
            for (int c2 = 0; c2 < 3; c2++)
                v[r2][c2] = tile[yq + r2][xl + c2];
#pragma unroll
        for (int ky = 0; ky < 3; ky++)
#pragma unroll
            for (int kx = 0; kx < 3; kx++) {
                int tap = ky * 3 + kx;
                ull w0 = swp[cp][tap][0];
                ull w1 = swp[cp][tap][1];
                ull w2 = swp[cp][tap][2];
#pragma unroll
                for (int oy = 0; oy < 4; oy++) {
                    ull val = v[oy + ky][kx];
                    acc[oy][0] = ffma2(w0, val, acc[oy][0]);
                    acc[oy][1] = ffma2(w1, val, acc[oy][1]);
                    acc[oy][2] = ffma2(w2, val, acc[oy][2]);
                }
            }
        __syncthreads();
    }
    float tb0 = __ldg(tb + 0), tb1 = __ldg(tb + 1), tb2 = __ldg(tb + 2);
#pragma unroll
    for (int oy = 0; oy < 4; oy++) {
        int row = (y0 + yq + oy) * 512 + x0 + xl;
        float2 a0 = upk2(acc[oy][0]);
        float2 a1 = upk2(acc[oy][1]);
        float2 a2 = upk2(acc[oy][2]);
        g_pred4[row] = make_float4(tb0 + a0.x + a0.y,
                                   tb1 + a1.x + a1.y,
                                   tb2 + a2.x + a2.y, 0.f);
    }
}

// ---------------- K5: query gather ----------------
__global__ void gather_kernel(const float* __restrict__ coord,
                              const float* __restrict__ cell,
                              float* __restrict__ out) {
    int q = blockIdx.x * 256 + threadIdx.x;
    float2 cd = __ldg((const float2*)coord + q);
    float2 cl = __ldg((const float2*)cell + q);
    const float LO = -0.999999f, HI = 0.999999f;
    float gyq = fminf(fmaxf(cd.x - cl.x * 0.5f + 1e-6f, LO), HI);
    float gxq = fminf(fmaxf(cd.y - cl.y * 0.5f + 1e-6f, LO), HI);
    int xi = (int)rintf((gxq + 1.0f) * 0.5f * 511.0f);
    int yi = (int)rintf((gyq + 1.0f) * 0.5f * 511.0f);
    xi = min(511, max(0, xi));
    yi = min(511, max(0, yi));
    float4 v = __ldg(&g_pred4[(yi << 9) + xi]);
    out[q * 3 + 0] = v.x;
    out[q * 3 + 1] = v.y;
    out[q * 3 + 2] = v.z;
}

// ---------------- launch ----------------
extern "C" void kernel_launch(void* const* d_in, const int* in_sizes, int n_in,
                              void* d_out, int out_size) {
    const float* inp   = (const float*)d_in[0];
    const float* coord = (const float*)d_in[1];
    const float* cell  = (const float*)d_in[2];
    const float* enc_w = (const float*)d_in[3];
    const float* enc_b = (const float*)d_in[4];
    const float* w1    = (const float*)d_in[5];
    const float* b1    = (const float*)d_in[6];
    const float* w2    = (const float*)d_in[7];
    const float* b2    = (const float*)d_in[8];
    const float* rw    = (const float*)d_in[9];
    const float* rb    = (const float*)d_in[10];
    const float* ow    = (const float*)d_in[11];
    const float* ob    = (const float*)d_in[12];
    const float* tw    = (const float*)d_in[13];
    const float* tb    = (const float*)d_in[14];
    const float* wc    = (const float*)d_in[15];
    const float* we    = (const float*)d_in[16];
    float* out = (float*)d_out;

    enc_kernel<<<2048, 256>>>(inp, enc_w, enc_b);
    phase_kernel<<<16, 64>>>(w1, b1, w2, b2, rw, rb, ow, ob, wc, we);
    af_kernel<<<1024, 256>>>();
    mid_kernel<<<512, 256>>>();
    main_kernel<<<dim3(512, 4), 256>>>();
    tail_kernel<<<dim3(4, 64), 256>>>(tw, tb);
    gather_kernel<<<1024, 256>>>(coord, cell, out);
}

// round 9
// speedup vs baseline: 1.7740x; 1.5089x over previous
#include <cuda_runtime.h>
#include <math.h>

typedef unsigned long long ull;

// ---------------- f32x2 packed helpers (Blackwell) ----------------
__device__ __forceinline__ ull pk2(float lo, float hi) {
    ull r; asm("mov.b64 %0, {%1,%2};" : "=l"(r) : "f"(lo), "f"(hi)); return r;
}
__device__ __forceinline__ float2 upk2(ull v) {
    float2 r; asm("mov.b64 {%0,%1}, %2;" : "=f"(r.x), "=f"(r.y) : "l"(v)); return r;
}
__device__ __forceinline__ ull ffma2(ull a, ull b, ull c) {
    ull d; asm("fma.rn.f32x2 %0, %1, %2, %3;" : "=l"(d) : "l"(a), "l"(b), "l"(c)); return d;
}

// ---------------- device scratch ----------------
__device__ __align__(16) float4 g_feat4[16 * 16384];  // enc output, [quad][y][x] (4 ch)
__device__ __align__(16) float4 g_pred4[512 * 512];   // tail output, (r,g,b,_)
__device__ float g_off[32];                           // per-phase offsets
__device__ float g_A[16 * 512];                       // [ph][k][c]
__device__ float g_B[16 * 512];                       // [ph][c][k]
__device__ __align__(16) ull g_AF2[16 * 4 * 16384];   // A_ph @ feat, [ph][kpair][pos]
__device__ __align__(16) ull g_TB[1728];              // [ph][tap][o][kp] packed k-pairs
__device__ __align__(16) ull g_TWq[864];              // [q][tap][o][half] packed ch-pairs

// ---------------- K1: enc conv3x3, pad=1, 3->64 ch, quad output ----------------
__global__ void __launch_bounds__(256) enc_kernel(const float* __restrict__ inp,
                                                  const float* __restrict__ w,
                                                  const float* __restrict__ b) {
    __shared__ float sw[108];
    __shared__ float sb[4];
    int tid = threadIdx.x;
    int idx = blockIdx.x * 256 + tid;        // quad*16384 + y*128 + x
    int quad = idx >> 14;
    if (tid < 108) sw[tid] = w[quad * 108 + tid];
    if (tid < 4)   sb[tid] = b[quad * 4 + tid];
    __syncthreads();
    int rem = idx & 16383, y = rem >> 7, x = rem & 127;
    float a0 = sb[0], a1 = sb[1], a2 = sb[2], a3 = sb[3];
#pragma unroll
    for (int ci = 0; ci < 3; ci++) {
        const float* ip = inp + ci * 16384;
#pragma unroll
        for (int ky = 0; ky < 3; ky++) {
            int yy = y + ky - 1;
            if (yy < 0 || yy > 127) continue;
#pragma unroll
            for (int kx = 0; kx < 3; kx++) {
                int xx = x + kx - 1;
                if (xx < 0 || xx > 127) continue;
                float v = __ldg(ip + yy * 128 + xx);
                int t = ci * 9 + ky * 3 + kx;
                a0 += v * sw[t]; a1 += v * sw[27 + t];
                a2 += v * sw[54 + t]; a3 += v * sw[81 + t];
            }
        }
    }
    g_feat4[idx] = make_float4(a0, a1, a2, a3);
}

// ---------------- K2: per-phase MLP -> off, A, B ----------------
__global__ void phase_kernel(const float* __restrict__ w1, const float* __restrict__ b1,
                             const float* __restrict__ w2, const float* __restrict__ b2,
                             const float* __restrict__ rw, const float* __restrict__ rb,
                             const float* __restrict__ ow, const float* __restrict__ ob,
                             const float* __restrict__ wc, const float* __restrict__ we) {
    __shared__ float s1[64], s2[64], sr[4];
    int c = threadIdx.x;
    int ph = blockIdx.x;                 // ph = (y%4)*4 + (x%4)
    float chv = ((ph >> 2) + 0.5f) * 0.25f - 0.5f;
    float cwv = ((ph & 3)  + 0.5f) * 0.25f - 0.5f;
    float e1 = b1[c] + w1[c * 4 + 0] * 0.25f + w1[c * 4 + 1] * 0.25f
                     + w1[c * 4 + 2] * chv   + w1[c * 4 + 3] * cwv;
    s1[c] = fmaxf(e1, 0.f);
    __syncthreads();
    float e2 = b2[c];
    for (int d = 0; d < 64; d++) e2 += w2[c * 64 + d] * s1[d];
    s2[c] = fmaxf(e2, 0.f);
    __syncthreads();
    if (c < 4) {
        float z = rb[c];
        for (int d = 0; d < 64; d++) z += rw[c * 64 + d] * s2[d];
        sr[c] = 1.f / (1.f + expf(-z));
    } else if (c < 6) {
        int o = c - 4;
        float z = ob[o];
        for (int d = 0; d < 64; d++) z += ow[o * 64 + d] * s2[d];
        g_off[ph * 2 + o] = z;
    }
    __syncthreads();
    float r0 = sr[0], r1 = sr[1], r2 = sr[2], r3 = sr[3];
    for (int t = c; t < 512; t += 64) {
        g_A[ph * 512 + t] = r0 * wc[t] + r1 * wc[512 + t] + r2 * wc[1024 + t] + r3 * wc[1536 + t];
        g_B[ph * 512 + t] = r0 * we[t] + r1 * we[512 + t] + r2 * we[1024 + t] + r3 * we[1536 + t];
    }
}

// ---------------- K2b: AF[ph][kpair][pos] = packed A_ph @ feat ----------------
__global__ void __launch_bounds__(256) af_kernel() {
    __shared__ ull sA2[256];                 // [k][cpair] for this phase
    int tid = threadIdx.x;
    int ph = blockIdx.x >> 6;                // 16 phases x 64 chunks
    int chunk = blockIdx.x & 63;
    sA2[tid] = ((const ull*)g_A)[ph * 256 + tid];
    __syncthreads();
    int pos = chunk * 256 + tid;

    ull f2[32];
    const ulonglong2* F = (const ulonglong2*)g_feat4;
#pragma unroll
    for (int qd = 0; qd < 16; qd++) {
        ulonglong2 v = __ldg(F + qd * 16384 + pos);
        f2[2 * qd] = v.x; f2[2 * qd + 1] = v.y;
    }
    float m[8];
#pragma unroll
    for (int k = 0; k < 8; k++) {
        ull acc = 0ULL;
#pragma unroll
        for (int i = 0; i < 32; i++) acc = ffma2(sA2[k * 32 + i], f2[i], acc);
        float2 a = upk2(acc);
        m[k] = a.x + a.y;
    }
#pragma unroll
    for (int kp = 0; kp < 4; kp++)
        g_AF2[(ph * 4 + kp) * 16384 + pos] = pk2(m[2 * kp], m[2 * kp + 1]);
}

// ---------------- K2c: pack TB = tw folded with B, and quad tail weights ----------------
__global__ void pack_kernel(const float* __restrict__ tw) {
    int t = blockIdx.x * 256 + threadIdx.x;
    if (t < 1728) {
        // idx = ph*108 + tap*12 + o*4 + kp
        int kp = t & 3, o = (t >> 2) % 3, tap = (t / 12) % 9, ph = t / 108;
        float lo = 0.f, hi = 0.f;
        for (int c = 0; c < 64; c++) {
            float wv = __ldg(tw + o * 576 + c * 9 + tap);
            lo += wv * g_B[ph * 512 + c * 8 + 2 * kp];
            hi += wv * g_B[ph * 512 + c * 8 + 2 * kp + 1];
        }
        g_TB[t] = pk2(lo, hi);
    } else if (t < 2592) {
        int u = t - 1728;          // ((q*9+tap)*3+o)*2+h
        int h = u & 1, o = (u >> 1) % 3, tap = (u / 6) % 9, q = u / 54;
        int c0 = 4 * q + 2 * h;
        g_TWq[u] = pk2(__ldg(tw + o * 576 + c0 * 9 + tap),
                       __ldg(tw + o * 576 + (c0 + 1) * 9 + tap));
    }
}

// ---------------- K3: FUSED out2 + tail conv ----------------
// block: 64x16 output tile; halo 66x18 = 1188 px; 16 quad chunks in smem tile.
__global__ void __launch_bounds__(256, 3) fused_kernel(const float* __restrict__ tb) {
    extern __shared__ __align__(16) char shm[];
    float4* sbilW = (float4*)shm;                     // [1188]  19008 B
    int*    sMeta = (int*)(shm + 19008);              // [1188]   4752 B
    ull*    smid  = (ull*)(shm + 23760);              // [4*1188] 38016 B (union)
    ulonglong2* tile = (ulonglong2*)(shm + 23760);    // [18*68]  19584 B (union)
    ull*    sTW   = (ull*)(shm + 23760 + 19584);      // [54]

    int tid = threadIdx.x;
    int x0 = blockIdx.x * 64, y0 = blockIdx.y * 16;
    int xl = tid & 63, yt = tid >> 6;

    // ---- phase 1a: bilinear staging for halo pixels ----
    for (int t = tid; t < 1188; t += 256) {
        int r = t / 66, cc = t - r * 66;
        int yy = y0 - 1 + r, xx = x0 - 1 + cc;
        float4 wv = make_float4(0.f, 0.f, 0.f, 0.f);
        int meta = (r * 68 + cc) << 20;
        if (yy >= 0 && yy < 512 && xx >= 0 && xx < 512) {
            int ph = ((yy & 3) << 2) | (xx & 3);
            float offx = __ldg(g_off + 2 * ph), offy = __ldg(g_off + 2 * ph + 1);
            const float C2 = 2.0f / 127.0f;
            float gx = ((xx + 0.5f) * 0.25f - 0.5f) * C2 - 1.0f + offx * C2;
            float gy = ((yy + 0.5f) * 0.25f - 0.5f) * C2 - 1.0f + offy * C2;
            float px = (gx + 1.0f) * 63.5f;
            float py = (gy + 1.0f) * 63.5f;
            float fx = floorf(px), fy = floorf(py);
            float wx1 = px - fx, wx0 = 1.f - wx1;
            float wy1 = py - fy, wy0 = 1.f - wy1;
            int ix0 = (int)fx, iy0 = (int)fy;
            float mx0 = (ix0 >= 0 && ix0 < 128) ? 1.f : 0.f;
            float mx1 = (ix0 + 1 >= 0 && ix0 + 1 < 128) ? 1.f : 0.f;
            float my0 = (iy0 >= 0 && iy0 < 128) ? 1.f : 0.f;
            float my1 = (iy0 + 1 >= 0 && iy0 + 1 < 128) ? 1.f : 0.f;
            int cx0 = min(127, max(0, ix0)), cx1 = min(127, max(0, ix0 + 1));
            int cy0 = min(127, max(0, iy0)), cy1 = min(127, max(0, iy0 + 1));
            wv = make_float4(wy0 * wx0 * my0 * mx0, wy0 * wx1 * my0 * mx1,
                             wy1 * wx0 * my1 * mx0, wy1 * wx1 * my1 * mx1);
            int o00 = (cy0 << 7) | cx0;
            meta |= o00 | ((cx1 - cx0) << 14) | ((cy1 - cy0) << 15) | (ph << 16);
        }
        sbilW[t] = wv;
        sMeta[t] = meta;
    }
    __syncthreads();

    // ---- phase 1b: mid halo = bilinear(AF) ----
    for (int t = tid; t < 1188; t += 256) {
        float4 wv = sbilW[t];
        int meta = sMeta[t];
        int o00 = meta & 16383, dx = (meta >> 14) & 1, dy7 = ((meta >> 15) & 1) << 7;
        int ph = (meta >> 16) & 15;
        ull w00 = pk2(wv.x, wv.x), w01 = pk2(wv.y, wv.y);
        ull w10 = pk2(wv.z, wv.z), w11 = pk2(wv.w, wv.w);
        int o01 = o00 + dx, o10 = o00 + dy7, o11 = o10 + dx;
        const ull* AFp = g_AF2 + ph * 4 * 16384;
#pragma unroll
        for (int kp = 0; kp < 4; kp++) {
            const ull* Q = AFp + kp * 16384;
            ull a = ffma2(w00, __ldg(Q + o00), 0ULL);
            ull bq = ffma2(w01, __ldg(Q + o01), 0ULL);
            a = ffma2(w10, __ldg(Q + o10), a);
            bq = ffma2(w11, __ldg(Q + o11), bq);
            float2 s1 = upk2(a), s2 = upk2(bq);
            smid[kp * 1188 + t] = pk2(s1.x + s2.x, s1.y + s2.y);
        }
    }
    __syncthreads();

    // ---- phase 2: mid-conv via TB (rank-8 correction folded into tail) ----
    ull acc[4][3];
#pragma unroll
    for (int i = 0; i < 4; i++)
#pragma unroll
        for (int o = 0; o < 3; o++) acc[i][o] = 0ULL;
#pragma unroll
    for (int i = 0; i < 4; i++) {
        int yo = 4 * yt + i;
#pragma unroll
        for (int ky = 0; ky < 3; ky++) {
#pragma unroll
            for (int kx = 0; kx < 3; kx++) {
                int hidx = (yo + ky) * 66 + xl + kx;
                int ph = (sMeta[hidx] >> 16) & 15;
                const ulonglong2* TBp = (const ulonglong2*)(g_TB + ph * 108 + (ky * 3 + kx) * 12);
                ull m0 = smid[hidx], m1 = smid[1188 + hidx];
                ull m2 = smid[2376 + hidx], m3 = smid[3564 + hidx];
                ulonglong2 t0 = __ldg(TBp + 0), t1 = __ldg(TBp + 1);
                acc[i][0] = ffma2(t0.x, m0, acc[i][0]); acc[i][0] = ffma2(t0.y, m1, acc[i][0]);
                acc[i][0] = ffma2(t1.x, m2, acc[i][0]); acc[i][0] = ffma2(t1.y, m3, acc[i][0]);
                t0 = __ldg(TBp + 2); t1 = __ldg(TBp + 3);
                acc[i][1] = ffma2(t0.x, m0, acc[i][1]); acc[i][1] = ffma2(t0.y, m1, acc[i][1]);
                acc[i][1] = ffma2(t1.x, m2, acc[i][1]); acc[i][1] = ffma2(t1.y, m3, acc[i][1]);
                t0 = __ldg(TBp + 4); t1 = __ldg(TBp + 5);
                acc[i][2] = ffma2(t0.x, m0, acc[i][2]); acc[i][2] = ffma2(t0.y, m1, acc[i][2]);
                acc[i][2] = ffma2(t1.x, m2, acc[i][2]); acc[i][2] = ffma2(t1.y, m3, acc[i][2]);
            }
        }
    }
    __syncthreads();   // release smid region for tile reuse

    // ---- phase 3: 16 quad chunks: stage out2 tile (bil of feat), conv ----
    for (int q = 0; q < 16; q++) {
        if (tid < 54) sTW[tid] = __ldg(g_TWq + q * 54 + tid);
        const ulonglong2* F = (const ulonglong2*)g_feat4 + q * 16384;
        for (int t = tid; t < 1188; t += 256) {
            float4 wv = sbilW[t];
            int meta = sMeta[t];
            int o00 = meta & 16383, dx = (meta >> 14) & 1, dy7 = ((meta >> 15) & 1) << 7;
            int o01 = o00 + dx, o10 = o00 + dy7, o11 = o10 + dx;
            ull w00 = pk2(wv.x, wv.x), w01 = pk2(wv.y, wv.y);
            ull w10 = pk2(wv.z, wv.z), w11 = pk2(wv.w, wv.w);
            ulonglong2 v00 = __ldg(F + o00), v01 = __ldg(F + o01);
            ulonglong2 v10 = __ldg(F + o10), v11 = __ldg(F + o11);
            ull lo = ffma2(w00, v00.x, 0ULL), hi = ffma2(w00, v00.y, 0ULL);
            lo = ffma2(w01, v01.x, lo); hi = ffma2(w01, v01.y, hi);
            lo = ffma2(w10, v10.x, lo); hi = ffma2(w10, v10.y, hi);
            lo = ffma2(w11, v11.x, lo); hi = ffma2(w11, v11.y, hi);
            tile[(meta >> 20) & 2047] = make_ulonglong2(lo, hi);
        }
        __syncthreads();
#pragma unroll
        for (int ky = 0; ky < 3; ky++) {
#pragma unroll
            for (int kx = 0; kx < 3; kx++) {
                const ull* W = sTW + (ky * 3 + kx) * 6;
                ull w0l = W[0], w0h = W[1], w1l = W[2], w1h = W[3], w2l = W[4], w2h = W[5];
#pragma unroll
                for (int i = 0; i < 4; i++) {
                    ulonglong2 v = tile[(4 * yt + i + ky) * 68 + xl + kx];
                    acc[i][0] = ffma2(w0l, v.x, acc[i][0]); acc[i][0] = ffma2(w0h, v.y, acc[i][0]);
                    acc[i][1] = ffma2(w1l, v.x, acc[i][1]); acc[i][1] = ffma2(w1h, v.y, acc[i][1]);
                    acc[i][2] = ffma2(w2l, v.x, acc[i][2]); acc[i][2] = ffma2(w2h, v.y, acc[i][2]);
                }
            }
        }
        __syncthreads();
    }

    float tb0 = __ldg(tb), tb1 = __ldg(tb + 1), tb2 = __ldg(tb + 2);
#pragma unroll
    for (int i = 0; i < 4; i++) {
        int yo = 4 * yt + i;
        float2 a0 = upk2(acc[i][0]), a1 = upk2(acc[i][1]), a2 = upk2(acc[i][2]);
        g_pred4[(y0 + yo) * 512 + x0 + xl] =
            make_float4(tb0 + a0.x + a0.y, tb1 + a1.x + a1.y, tb2 + a2.x + a2.y, 0.f);
    }
}

// ---------------- K5: query gather ----------------
__global__ void gather_kernel(const float* __restrict__ coord,
                              const float* __restrict__ cell,
                              float* __restrict__ out) {
    int q = blockIdx.x * 256 + threadIdx.x;
    float2 cd = __ldg((const float2*)coord + q);
    float2 cl = __ldg((const float2*)cell + q);
    const float LO = -0.999999f, HI = 0.999999f;
    float gyq = fminf(fmaxf(cd.x - cl.x * 0.5f + 1e-6f, LO), HI);
    float gxq = fminf(fmaxf(cd.y - cl.y * 0.5f + 1e-6f, LO), HI);
    int xi = (int)rintf((gxq + 1.0f) * 0.5f * 511.0f);
    int yi = (int)rintf((gyq + 1.0f) * 0.5f * 511.0f);
    xi = min(511, max(0, xi));
    yi = min(511, max(0, yi));
    float4 v = __ldg(&g_pred4[(yi << 9) + xi]);
    out[q * 3 + 0] = v.x;
    out[q * 3 + 1] = v.y;
    out[q * 3 + 2] = v.z;
}

// ---------------- launch ----------------
extern "C" void kernel_launch(void* const* d_in, const int* in_sizes, int n_in,
                              void* d_out, int out_size) {
    const float* inp   = (const float*)d_in[0];
    const float* coord = (const float*)d_in[1];
    const float* cell  = (const float*)d_in[2];
    const float* enc_w = (const float*)d_in[3];
    const float* enc_b = (const float*)d_in[4];
    const float* w1    = (const float*)d_in[5];
    const float* b1    = (const float*)d_in[6];
    const float* w2    = (const float*)d_in[7];
    const float* b2    = (const float*)d_in[8];
    const float* rw    = (const float*)d_in[9];
    const float* rb    = (const float*)d_in[10];
    const float* ow    = (const float*)d_in[11];
    const float* ob    = (const float*)d_in[12];
    const float* tw    = (const float*)d_in[13];
    const float* tb    = (const float*)d_in[14];
    const float* wc    = (const float*)d_in[15];
    const float* we    = (const float*)d_in[16];
    float* out = (float*)d_out;

    const int SHM = 19008 + 4752 + 38016;   // 61776 B
    static int configured = 0;
    cudaFuncSetAttribute(fused_kernel, cudaFuncAttributeMaxDynamicSharedMemorySize, SHM);
    (void)configured;

    enc_kernel<<<1024, 256>>>(inp, enc_w, enc_b);
    phase_kernel<<<16, 64>>>(w1, b1, w2, b2, rw, rb, ow, ob, wc, we);
    af_kernel<<<1024, 256>>>();
    pack_kernel<<<11, 256>>>(tw);
    fused_kernel<<<dim3(8, 32), 256, SHM>>>(tb);
    gather_kernel<<<1024, 256>>>(coord, cell, out);
}